// round 14
// baseline (speedup 1.0000x reference)
#include <cuda_runtime.h>
#include <math.h>

#define N_NODES 8192
#define D 256
#define MAXNNZ 128

// Scratch: ELL adjacency (4 matrices) + 8 feature buffers [8192,256] fp32
__device__ int   g_cols[4][N_NODES * MAXNNZ];
__device__ int   g_len[4][N_NODES];
__device__ float g_buf[8][N_NODES * D];

// ---------------------------------------------------------------------------
// Extract binary adjacency -> ELL. One warp per row, ballot compaction.
// 256 cols per iteration (2x float4/lane) + explicit next-iteration prefetch
// -> ~4 loads in flight per warp while the ballot chain runs (was MLP~1).
// Output ordering identical to the serial version (column-major scan).
// ---------------------------------------------------------------------------
__device__ __forceinline__ void extract_chunk128(
    float4 v, int c0, int lane, int* cols, int& base)
{
    float vv[4] = {v.x, v.y, v.z, v.w};
    #pragma unroll
    for (int j = 0; j < 4; j++) {
        bool nz = (vv[j] != 0.0f);
        unsigned m = __ballot_sync(0xffffffffu, nz);
        if (nz) {
            int off = base + __popc(m & ((1u << lane) - 1u));
            if (off < MAXNNZ) cols[off] = c0 + lane * 4 + j;
        }
        base += __popc(m);
    }
}

__global__ void extract_kernel(const float* __restrict__ a0,
                               const float* __restrict__ a1,
                               const float* __restrict__ a2,
                               const float* __restrict__ a3)
{
    int gw   = (blockIdx.x * blockDim.x + threadIdx.x) >> 5;
    int lane = threadIdx.x & 31;
    int mat  = gw >> 13;
    int row  = gw & (N_NODES - 1);
    const float* A = (mat == 0) ? a0 : (mat == 1) ? a1 : (mat == 2) ? a2 : a3;
    const float* arow = A + (size_t)row * N_NODES;
    int* cols = &g_cols[mat][row * MAXNNZ];
    int base = 0;

    float4 cur0 = *(const float4*)(arow + lane * 4);
    float4 cur1 = *(const float4*)(arow + 128 + lane * 4);
    for (int c0 = 0; c0 < N_NODES; c0 += 256) {
        float4 nxt0, nxt1;
        if (c0 + 256 < N_NODES) {
            nxt0 = *(const float4*)(arow + c0 + 256 + lane * 4);
            nxt1 = *(const float4*)(arow + c0 + 384 + lane * 4);
        }
        extract_chunk128(cur0, c0,       lane, cols, base);
        extract_chunk128(cur1, c0 + 128, lane, cols, base);
        cur0 = nxt0;
        cur1 = nxt1;
    }
    if (lane == 0) g_len[mat][row] = base < MAXNNZ ? base : MAXNNZ;
}

// ---------------------------------------------------------------------------
// cp.async helpers
// ---------------------------------------------------------------------------
__device__ __forceinline__ unsigned smem_u32(const void* p) {
    return (unsigned)__cvta_generic_to_shared(p);
}
__device__ __forceinline__ void cp16(unsigned dst, const float* src) {
    asm volatile("cp.async.cg.shared.global [%0], [%1], 16;" :: "r"(dst), "l"(src));
}
__device__ __forceinline__ void cp_commit() {
    asm volatile("cp.async.commit_group;");
}
template <int N>
__device__ __forceinline__ void cp_wait() {
    asm volatile("cp.async.wait_group %0;" :: "n"(N));
}

__device__ __forceinline__ void mma_tf32(float* c, const unsigned* a, const unsigned* b) {
    asm volatile(
        "mma.sync.aligned.m16n8k8.row.col.f32.tf32.tf32.f32 "
        "{%0,%1,%2,%3}, {%4,%5,%6,%7}, {%8,%9}, {%0,%1,%2,%3};"
        : "+f"(c[0]), "+f"(c[1]), "+f"(c[2]), "+f"(c[3])
        : "r"(a[0]), "r"(a[1]), "r"(a[2]), "r"(a[3]), "r"(b[0]), "r"(b[1]));
}

#define BK 32       // K per chunk
#define SST 36      // smem row stride in floats (36 mod 32 = 4 -> conflict-free)
#define NSTAGE 3    // cp.async ring stages
#define PD 2        // prefetch distance
#define STAGE_T (128 * SST)                              // floats per tile stage
#define GEMM_SMEM_BYTES (2 * NSTAGE * STAGE_T * 4)       // 110592 bytes

// ---------------------------------------------------------------------------
// Fused 6-in-1 tf32 tensor-core GEMM, cp.async 3-stage BK=32 pipeline.
// Block tile 128x128, 256 threads, 8 warps x (32x64) m16n8k8.
// grid = (12, 64). mats 0..2 use X0, 3..5 use X1. Ci = X @ Wi^T + bi.
// Race-free ordering: wait(group kc) -> __syncthreads() -> refill kc+PD
// -> compute kc.
// ---------------------------------------------------------------------------
__global__ void __launch_bounds__(256) gemm6_mma(
    const float* __restrict__ X0, const float* __restrict__ X1,
    const float* __restrict__ W0, const float* __restrict__ W1, const float* __restrict__ W2,
    const float* __restrict__ W3, const float* __restrict__ W4, const float* __restrict__ W5,
    const float* __restrict__ b0, const float* __restrict__ b1, const float* __restrict__ b2,
    const float* __restrict__ b3, const float* __restrict__ b4, const float* __restrict__ b5,
    float* __restrict__ C0, float* __restrict__ C1, float* __restrict__ C2,
    float* __restrict__ C3, float* __restrict__ C4, float* __restrict__ C5, int K)
{
    extern __shared__ float smem[];
    float* Asm = smem;
    float* Bsm = smem + NSTAGE * STAGE_T;

    int tid  = threadIdx.x;
    int mat  = blockIdx.x >> 1;
    int n0   = (blockIdx.x & 1) * 128;
    int m0   = blockIdx.y * 128;

    const float* X = (mat < 3) ? X0 : X1;
    const float* W = (mat == 0) ? W0 : (mat == 1) ? W1 : (mat == 2) ? W2 :
                     (mat == 3) ? W3 : (mat == 4) ? W4 : W5;
    const float* bias = (mat == 0) ? b0 : (mat == 1) ? b1 : (mat == 2) ? b2 :
                        (mat == 3) ? b3 : (mat == 4) ? b4 : b5;
    float* C = (mat == 0) ? C0 : (mat == 1) ? C1 : (mat == 2) ? C2 :
               (mat == 3) ? C3 : (mat == 4) ? C4 : C5;

    int wid = tid >> 5, lane = tid & 31;
    int wm = (wid >> 1) * 32;
    int wn = (wid & 1) * 64;
    int gid = lane >> 2;
    int tg  = lane & 3;

    int lrow = tid >> 3;           // 0..31
    int lc   = (tid & 7) * 4;      // 0,4,...,28

    const float* xb = X + (size_t)(m0 + lrow) * K + lc;
    const float* wb = W + (size_t)(n0 + lrow) * K + lc;
    size_t rstep = (size_t)32 * K;
    unsigned adst = smem_u32(&Asm[lrow * SST + lc]);
    unsigned bdst = smem_u32(&Bsm[lrow * SST + lc]);
    const unsigned RST = 32 * SST * 4;
    const unsigned STB = STAGE_T * 4;

    float acc[2][8][4];
    #pragma unroll
    for (int i = 0; i < 2; i++)
        #pragma unroll
        for (int j = 0; j < 8; j++)
            #pragma unroll
            for (int k = 0; k < 4; k++) acc[i][j][k] = 0.0f;

    int nkc = K / BK;

    #pragma unroll
    for (int s = 0; s < PD; s++) {
        if (s < nkc) {
            int koff = s * BK;
            unsigned so = s * STB;
            #pragma unroll
            for (int r4 = 0; r4 < 4; r4++) {
                cp16(adst + so + r4 * RST, xb + r4 * rstep + koff);
                cp16(bdst + so + r4 * RST, wb + r4 * rstep + koff);
            }
            cp_commit();
        }
    }

    for (int kc = 0; kc < nkc; kc++) {
        int rem = nkc - 1 - kc;
        if (rem >= 1) cp_wait<1>();
        else          cp_wait<0>();
        __syncthreads();
        if (kc + PD < nkc) {
            int koff = (kc + PD) * BK;
            unsigned so = ((kc + PD) % NSTAGE) * STB;
            #pragma unroll
            for (int r4 = 0; r4 < 4; r4++) {
                cp16(adst + so + r4 * RST, xb + r4 * rstep + koff);
                cp16(bdst + so + r4 * RST, wb + r4 * rstep + koff);
            }
            cp_commit();
        }
        const float* Ab = Asm + (kc % NSTAGE) * STAGE_T;
        const float* Bb = Bsm + (kc % NSTAGE) * STAGE_T;
        #pragma unroll
        for (int k8 = 0; k8 < BK; k8 += 8) {
            unsigned a[2][4];
            #pragma unroll
            for (int mt = 0; mt < 2; mt++) {
                int r = wm + mt * 16 + gid;
                a[mt][0] = __float_as_uint(Ab[(r)     * SST + k8 + tg]);
                a[mt][1] = __float_as_uint(Ab[(r + 8) * SST + k8 + tg]);
                a[mt][2] = __float_as_uint(Ab[(r)     * SST + k8 + tg + 4]);
                a[mt][3] = __float_as_uint(Ab[(r + 8) * SST + k8 + tg + 4]);
            }
            #pragma unroll
            for (int nt = 0; nt < 8; nt++) {
                int rn = wn + nt * 8 + gid;
                unsigned b[2];
                b[0] = __float_as_uint(Bb[rn * SST + k8 + tg]);
                b[1] = __float_as_uint(Bb[rn * SST + k8 + tg + 4]);
                mma_tf32(acc[0][nt], a[0], b);
                mma_tf32(acc[1][nt], a[1], b);
            }
        }
    }

    #pragma unroll
    for (int mt = 0; mt < 2; mt++) {
        #pragma unroll
        for (int nt = 0; nt < 8; nt++) {
            int col = n0 + wn + nt * 8 + tg * 2;
            float2 bv = *(const float2*)(bias + col);
            int r0 = m0 + wm + mt * 16 + gid;
            float2 o0 = {acc[mt][nt][0] + bv.x, acc[mt][nt][1] + bv.y};
            float2 o1 = {acc[mt][nt][2] + bv.x, acc[mt][nt][3] + bv.y};
            *(float2*)(C + (size_t)r0 * D + col)       = o0;
            *(float2*)(C + (size_t)(r0 + 8) * D + col) = o1;
        }
    }
}

// ---------------------------------------------------------------------------
// Fused dual combine: blocks [0,2048) config P, [2048,4096) config Q.
// float4, 64 thr/row, 4 rows/block. Optional fused L2 row norm.
// ---------------------------------------------------------------------------
__global__ void __launch_bounds__(256) combine2x_kernel(
    const float* __restrict__ P0, const float* __restrict__ XA0, const float* __restrict__ XB0,
    int mA0, int mB0, float* __restrict__ out0,
    const float* __restrict__ P1, const float* __restrict__ XA1, const float* __restrict__ XB1,
    int mA1, int mB1, float* __restrict__ out1,
    int do_norm)
{
    __shared__ int sA[4][MAXNNZ];
    __shared__ int sB[4][MAXNNZ];
    __shared__ float red[4][2];

    int blk = blockIdx.x;
    const float *P, *XA, *XB;
    float* out;
    int matA, matB, rowbase;
    if (blk < 2048) {
        P = P0; XA = XA0; XB = XB0; out = out0; matA = mA0; matB = mB0;
        rowbase = blk * 4;
    } else {
        P = P1; XA = XA1; XB = XB1; out = out1; matA = mA1; matB = mB1;
        rowbase = (blk - 2048) * 4;
    }

    int tid = threadIdx.x;
    int r   = tid >> 6;
    int t   = tid & 63;
    int row = rowbase + r;

    int lenA = g_len[matA][row];
    int lenB = g_len[matB][row];
    {
        const int* cA = &g_cols[matA][row * MAXNNZ];
        const int* cB = &g_cols[matB][row * MAXNNZ];
        if (t      < lenA) sA[r][t]      = cA[t];
        if (t + 64 < lenA) sA[r][t + 64] = cA[t + 64];
        if (t      < lenB) sB[r][t]      = cB[t];
        if (t + 64 < lenB) sB[r][t + 64] = cB[t + 64];
    }
    __syncthreads();

    int c4 = t * 4;
    float4 acc = *(const float4*)(P + (size_t)row * D + c4);
    #pragma unroll 4
    for (int i = 0; i < lenA; i++) {
        float4 v = *(const float4*)(XA + (size_t)sA[r][i] * D + c4);
        acc.x += v.x; acc.y += v.y; acc.z += v.z; acc.w += v.w;
    }
    #pragma unroll 4
    for (int i = 0; i < lenB; i++) {
        float4 v = *(const float4*)(XB + (size_t)sB[r][i] * D + c4);
        acc.x += v.x; acc.y += v.y; acc.z += v.z; acc.w += v.w;
    }
    acc.x = acc.x > 0.0f ? acc.x : 0.1f * acc.x;
    acc.y = acc.y > 0.0f ? acc.y : 0.1f * acc.y;
    acc.z = acc.z > 0.0f ? acc.z : 0.1f * acc.z;
    acc.w = acc.w > 0.0f ? acc.w : 0.1f * acc.w;

    if (do_norm) {
        float s = acc.x * acc.x + acc.y * acc.y + acc.z * acc.z + acc.w * acc.w;
        #pragma unroll
        for (int off = 16; off > 0; off >>= 1)
            s += __shfl_xor_sync(0xffffffffu, s, off);
        if ((t & 31) == 0) red[r][t >> 5] = s;
        __syncthreads();
        float inv = 1.0f / (sqrtf(red[r][0] + red[r][1]) + 1e-9f);
        acc.x *= inv; acc.y *= inv; acc.z *= inv; acc.w *= inv;
    }
    *(float4*)(out + (size_t)row * D + c4) = acc;
}

// ---------------------------------------------------------------------------
extern "C" void kernel_launch(void* const* d_in, const int* in_sizes, int n_in,
                              void* d_out, int out_size)
{
    const float* hp         = (const float*)d_in[0];
    const float* hq         = (const float*)d_in[1];
    const float* a_cons     = (const float*)d_in[2];
    const float* a_prod     = (const float*)d_in[3];
    const float* a_rev_cons = (const float*)d_in[4];
    const float* a_rev_prod = (const float*)d_in[5];
    const float* w[12];
    const float* b[12];
    for (int i = 0; i < 12; i++) {
        w[i] = (const float*)d_in[6 + 2 * i];
        b[i] = (const float*)d_in[7 + 2 * i];
    }
    float* out = (float*)d_out;

    // Opt in to >48KB dynamic smem (idempotent; safe under graph capture).
    cudaFuncSetAttribute(gemm6_mma, cudaFuncAttributeMaxDynamicSharedMemorySize,
                         GEMM_SMEM_BYTES);

    void* symp = nullptr;
    cudaGetSymbolAddress(&symp, g_buf);
    float* B0 = (float*)symp;
    #define BUF(i) (B0 + (size_t)(i) * N_NODES * D)

    // adjacency ELL: 0=a_cons, 1=a_prod, 2=a_rev_cons, 3=a_rev_prod
    extract_kernel<<<4 * N_NODES / 8, 256>>>(a_cons, a_prod, a_rev_cons, a_rev_prod);

    dim3 gg(12, N_NODES / 128), gb(256);
    // ---- layer 1 (K = 512) ----
    gemm6_mma<<<gg, gb, GEMM_SMEM_BYTES>>>(hp, hq,
                          w[0], w[4], w[5], w[1], w[2], w[3],
                          b[0], b[4], b[5], b[1], b[2], b[3],
                          BUF(0), BUF(4), BUF(5), BUF(1), BUF(2), BUF(3), 512);
    combine2x_kernel<<<4096, 256>>>(
        BUF(0), BUF(2), BUF(3), 0, 3, BUF(6),
        BUF(1), BUF(4), BUF(5), 1, 2, BUF(7), 0);

    // ---- layer 2 (K = 256) ----
    gemm6_mma<<<gg, gb, GEMM_SMEM_BYTES>>>(BUF(6), BUF(7),
                          w[6], w[10], w[11], w[7], w[8], w[9],
                          b[6], b[10], b[11], b[7], b[8], b[9],
                          BUF(0), BUF(4), BUF(5), BUF(1), BUF(2), BUF(3), 256);
    combine2x_kernel<<<4096, 256>>>(
        BUF(0), BUF(2), BUF(3), 0, 3, out,
        BUF(1), BUF(4), BUF(5), 1, 2, out + (size_t)N_NODES * D, 1);
    #undef BUF
}

// round 15
// speedup vs baseline: 1.0956x; 1.0956x over previous
#include <cuda_runtime.h>
#include <cuda_fp16.h>
#include <math.h>

#define N_NODES 8192
#define D 256
#define MAXNNZ 128

// Scratch: ELL adjacency (4 matrices) + 8 feature buffers [8192,256] fp32-sized.
// BUF(2..5) hold fp16 data (reinterpreted), BUF(0,1,6,7) hold fp32.
__device__ int   g_cols[4][N_NODES * MAXNNZ];
__device__ int   g_len[4][N_NODES];
__device__ float g_buf[8][N_NODES * D];

// ---------------------------------------------------------------------------
// Extract binary adjacency -> ELL. One warp per row, ballot compaction.
// (R13 version: R10 skip and R14 prefetch both regressed; reverted.)
// ---------------------------------------------------------------------------
__global__ void extract_kernel(const float* __restrict__ a0,
                               const float* __restrict__ a1,
                               const float* __restrict__ a2,
                               const float* __restrict__ a3)
{
    int gw   = (blockIdx.x * blockDim.x + threadIdx.x) >> 5;
    int lane = threadIdx.x & 31;
    int mat  = gw >> 13;
    int row  = gw & (N_NODES - 1);
    const float* A = (mat == 0) ? a0 : (mat == 1) ? a1 : (mat == 2) ? a2 : a3;
    const float* arow = A + (size_t)row * N_NODES;
    int* cols = &g_cols[mat][row * MAXNNZ];
    int base = 0;
    for (int c0 = 0; c0 < N_NODES; c0 += 128) {
        float4 v = *(const float4*)(arow + c0 + lane * 4);
        float vv[4] = {v.x, v.y, v.z, v.w};
        #pragma unroll
        for (int j = 0; j < 4; j++) {
            bool nz = (vv[j] != 0.0f);
            unsigned m = __ballot_sync(0xffffffffu, nz);
            if (nz) {
                int off = base + __popc(m & ((1u << lane) - 1u));
                if (off < MAXNNZ) cols[off] = c0 + lane * 4 + j;
            }
            base += __popc(m);
        }
    }
    if (lane == 0) g_len[mat][row] = base < MAXNNZ ? base : MAXNNZ;
}

// ---------------------------------------------------------------------------
// cp.async helpers
// ---------------------------------------------------------------------------
__device__ __forceinline__ unsigned smem_u32(const void* p) {
    return (unsigned)__cvta_generic_to_shared(p);
}
__device__ __forceinline__ void cp16(unsigned dst, const float* src) {
    asm volatile("cp.async.cg.shared.global [%0], [%1], 16;" :: "r"(dst), "l"(src));
}
__device__ __forceinline__ void cp_commit() {
    asm volatile("cp.async.commit_group;");
}
template <int N>
__device__ __forceinline__ void cp_wait() {
    asm volatile("cp.async.wait_group %0;" :: "n"(N));
}

__device__ __forceinline__ void mma_tf32(float* c, const unsigned* a, const unsigned* b) {
    asm volatile(
        "mma.sync.aligned.m16n8k8.row.col.f32.tf32.tf32.f32 "
        "{%0,%1,%2,%3}, {%4,%5,%6,%7}, {%8,%9}, {%0,%1,%2,%3};"
        : "+f"(c[0]), "+f"(c[1]), "+f"(c[2]), "+f"(c[3])
        : "r"(a[0]), "r"(a[1]), "r"(a[2]), "r"(a[3]), "r"(b[0]), "r"(b[1]));
}

#define BK 32       // K per chunk
#define SST 36      // smem row stride in floats (36 mod 32 = 4 -> conflict-free)
#define NSTAGE 3    // cp.async ring stages
#define PD 2        // prefetch distance
#define STAGE_T (128 * SST)                              // floats per tile stage
#define GEMM_SMEM_BYTES (2 * NSTAGE * STAGE_T * 4)       // 110592 bytes

// ---------------------------------------------------------------------------
// Fused 6-in-1 tf32 tensor-core GEMM, cp.async 3-stage BK=32 pipeline.
// Block tile 128x128, 256 threads, 8 warps x (32x64) m16n8k8.
// grid = (12, 64). mats 0..2 use X0, 3..5 use X1. Ci = X @ Wi^T + bi.
// mats 0 and 3 (self-path) store fp32; mats 1,2,4,5 (gather-path) store fp16.
// Race-free ordering: wait(group kc) -> __syncthreads() -> refill kc+PD
// -> compute kc.
// ---------------------------------------------------------------------------
__global__ void __launch_bounds__(256) gemm6_mma(
    const float* __restrict__ X0, const float* __restrict__ X1,
    const float* __restrict__ W0, const float* __restrict__ W1, const float* __restrict__ W2,
    const float* __restrict__ W3, const float* __restrict__ W4, const float* __restrict__ W5,
    const float* __restrict__ b0, const float* __restrict__ b1, const float* __restrict__ b2,
    const float* __restrict__ b3, const float* __restrict__ b4, const float* __restrict__ b5,
    float* __restrict__ C0, float* __restrict__ C1, float* __restrict__ C2,
    float* __restrict__ C3, float* __restrict__ C4, float* __restrict__ C5, int K)
{
    extern __shared__ float smem[];
    float* Asm = smem;
    float* Bsm = smem + NSTAGE * STAGE_T;

    int tid  = threadIdx.x;
    int mat  = blockIdx.x >> 1;
    int n0   = (blockIdx.x & 1) * 128;
    int m0   = blockIdx.y * 128;

    const float* X = (mat < 3) ? X0 : X1;
    const float* W = (mat == 0) ? W0 : (mat == 1) ? W1 : (mat == 2) ? W2 :
                     (mat == 3) ? W3 : (mat == 4) ? W4 : W5;
    const float* bias = (mat == 0) ? b0 : (mat == 1) ? b1 : (mat == 2) ? b2 :
                        (mat == 3) ? b3 : (mat == 4) ? b4 : b5;
    float* C = (mat == 0) ? C0 : (mat == 1) ? C1 : (mat == 2) ? C2 :
               (mat == 3) ? C3 : (mat == 4) ? C4 : C5;
    bool half_out = (mat != 0) && (mat != 3);

    int wid = tid >> 5, lane = tid & 31;
    int wm = (wid >> 1) * 32;
    int wn = (wid & 1) * 64;
    int gid = lane >> 2;
    int tg  = lane & 3;

    int lrow = tid >> 3;           // 0..31
    int lc   = (tid & 7) * 4;      // 0,4,...,28

    const float* xb = X + (size_t)(m0 + lrow) * K + lc;
    const float* wb = W + (size_t)(n0 + lrow) * K + lc;
    size_t rstep = (size_t)32 * K;
    unsigned adst = smem_u32(&Asm[lrow * SST + lc]);
    unsigned bdst = smem_u32(&Bsm[lrow * SST + lc]);
    const unsigned RST = 32 * SST * 4;
    const unsigned STB = STAGE_T * 4;

    float acc[2][8][4];
    #pragma unroll
    for (int i = 0; i < 2; i++)
        #pragma unroll
        for (int j = 0; j < 8; j++)
            #pragma unroll
            for (int k = 0; k < 4; k++) acc[i][j][k] = 0.0f;

    int nkc = K / BK;

    #pragma unroll
    for (int s = 0; s < PD; s++) {
        if (s < nkc) {
            int koff = s * BK;
            unsigned so = s * STB;
            #pragma unroll
            for (int r4 = 0; r4 < 4; r4++) {
                cp16(adst + so + r4 * RST, xb + r4 * rstep + koff);
                cp16(bdst + so + r4 * RST, wb + r4 * rstep + koff);
            }
            cp_commit();
        }
    }

    for (int kc = 0; kc < nkc; kc++) {
        int rem = nkc - 1 - kc;
        if (rem >= 1) cp_wait<1>();
        else          cp_wait<0>();
        __syncthreads();
        if (kc + PD < nkc) {
            int koff = (kc + PD) * BK;
            unsigned so = ((kc + PD) % NSTAGE) * STB;
            #pragma unroll
            for (int r4 = 0; r4 < 4; r4++) {
                cp16(adst + so + r4 * RST, xb + r4 * rstep + koff);
                cp16(bdst + so + r4 * RST, wb + r4 * rstep + koff);
            }
            cp_commit();
        }
        const float* Ab = Asm + (kc % NSTAGE) * STAGE_T;
        const float* Bb = Bsm + (kc % NSTAGE) * STAGE_T;
        #pragma unroll
        for (int k8 = 0; k8 < BK; k8 += 8) {
            unsigned a[2][4];
            #pragma unroll
            for (int mt = 0; mt < 2; mt++) {
                int r = wm + mt * 16 + gid;
                a[mt][0] = __float_as_uint(Ab[(r)     * SST + k8 + tg]);
                a[mt][1] = __float_as_uint(Ab[(r + 8) * SST + k8 + tg]);
                a[mt][2] = __float_as_uint(Ab[(r)     * SST + k8 + tg + 4]);
                a[mt][3] = __float_as_uint(Ab[(r + 8) * SST + k8 + tg + 4]);
            }
            #pragma unroll
            for (int nt = 0; nt < 8; nt++) {
                int rn = wn + nt * 8 + gid;
                unsigned b[2];
                b[0] = __float_as_uint(Bb[rn * SST + k8 + tg]);
                b[1] = __float_as_uint(Bb[rn * SST + k8 + tg + 4]);
                mma_tf32(acc[0][nt], a[0], b);
                mma_tf32(acc[1][nt], a[1], b);
            }
        }
    }

    // epilogue: add bias, store (fp16 for gather-path mats, fp32 for self-path)
    if (half_out) {
        __half* Ch = (__half*)C;
        #pragma unroll
        for (int mt = 0; mt < 2; mt++) {
            #pragma unroll
            for (int nt = 0; nt < 8; nt++) {
                int col = n0 + wn + nt * 8 + tg * 2;
                float2 bv = *(const float2*)(bias + col);
                int r0 = m0 + wm + mt * 16 + gid;
                __half2 h0 = __floats2half2_rn(acc[mt][nt][0] + bv.x, acc[mt][nt][1] + bv.y);
                __half2 h1 = __floats2half2_rn(acc[mt][nt][2] + bv.x, acc[mt][nt][3] + bv.y);
                *(__half2*)(Ch + (size_t)r0 * D + col)       = h0;
                *(__half2*)(Ch + (size_t)(r0 + 8) * D + col) = h1;
            }
        }
    } else {
        #pragma unroll
        for (int mt = 0; mt < 2; mt++) {
            #pragma unroll
            for (int nt = 0; nt < 8; nt++) {
                int col = n0 + wn + nt * 8 + tg * 2;
                float2 bv = *(const float2*)(bias + col);
                int r0 = m0 + wm + mt * 16 + gid;
                float2 o0 = {acc[mt][nt][0] + bv.x, acc[mt][nt][1] + bv.y};
                float2 o1 = {acc[mt][nt][2] + bv.x, acc[mt][nt][3] + bv.y};
                *(float2*)(C + (size_t)r0 * D + col)       = o0;
                *(float2*)(C + (size_t)(r0 + 8) * D + col) = o1;
            }
        }
    }
}

// ---------------------------------------------------------------------------
// Fused dual combine: blocks [0,2048) config P, [2048,4096) config Q.
// Gather buffers XA/XB are fp16 (half traffic); P and out are fp32.
// float4-width per thread (4 cols), 64 thr/row, 4 rows/block.
// ---------------------------------------------------------------------------
__global__ void __launch_bounds__(256) combine2x_kernel(
    const float* __restrict__ P0, const __half* __restrict__ XA0, const __half* __restrict__ XB0,
    int mA0, int mB0, float* __restrict__ out0,
    const float* __restrict__ P1, const __half* __restrict__ XA1, const __half* __restrict__ XB1,
    int mA1, int mB1, float* __restrict__ out1,
    int do_norm)
{
    __shared__ int sA[4][MAXNNZ];
    __shared__ int sB[4][MAXNNZ];
    __shared__ float red[4][2];

    int blk = blockIdx.x;
    const float* P;
    const __half *XA, *XB;
    float* out;
    int matA, matB, rowbase;
    if (blk < 2048) {
        P = P0; XA = XA0; XB = XB0; out = out0; matA = mA0; matB = mB0;
        rowbase = blk * 4;
    } else {
        P = P1; XA = XA1; XB = XB1; out = out1; matA = mA1; matB = mB1;
        rowbase = (blk - 2048) * 4;
    }

    int tid = threadIdx.x;
    int r   = tid >> 6;
    int t   = tid & 63;
    int row = rowbase + r;

    int lenA = g_len[matA][row];
    int lenB = g_len[matB][row];
    {
        const int* cA = &g_cols[matA][row * MAXNNZ];
        const int* cB = &g_cols[matB][row * MAXNNZ];
        if (t      < lenA) sA[r][t]      = cA[t];
        if (t + 64 < lenA) sA[r][t + 64] = cA[t + 64];
        if (t      < lenB) sB[r][t]      = cB[t];
        if (t + 64 < lenB) sB[r][t + 64] = cB[t + 64];
    }
    __syncthreads();

    int c4 = t * 4;
    float4 acc = *(const float4*)(P + (size_t)row * D + c4);
    #pragma unroll 4
    for (int i = 0; i < lenA; i++) {
        uint2 u = *(const uint2*)(XA + (size_t)sA[r][i] * D + c4);
        float2 f0 = __half22float2(*(__half2*)&u.x);
        float2 f1 = __half22float2(*(__half2*)&u.y);
        acc.x += f0.x; acc.y += f0.y; acc.z += f1.x; acc.w += f1.y;
    }
    #pragma unroll 4
    for (int i = 0; i < lenB; i++) {
        uint2 u = *(const uint2*)(XB + (size_t)sB[r][i] * D + c4);
        float2 f0 = __half22float2(*(__half2*)&u.x);
        float2 f1 = __half22float2(*(__half2*)&u.y);
        acc.x += f0.x; acc.y += f0.y; acc.z += f1.x; acc.w += f1.y;
    }
    acc.x = acc.x > 0.0f ? acc.x : 0.1f * acc.x;
    acc.y = acc.y > 0.0f ? acc.y : 0.1f * acc.y;
    acc.z = acc.z > 0.0f ? acc.z : 0.1f * acc.z;
    acc.w = acc.w > 0.0f ? acc.w : 0.1f * acc.w;

    if (do_norm) {
        float s = acc.x * acc.x + acc.y * acc.y + acc.z * acc.z + acc.w * acc.w;
        #pragma unroll
        for (int off = 16; off > 0; off >>= 1)
            s += __shfl_xor_sync(0xffffffffu, s, off);
        if ((t & 31) == 0) red[r][t >> 5] = s;
        __syncthreads();
        float inv = 1.0f / (sqrtf(red[r][0] + red[r][1]) + 1e-9f);
        acc.x *= inv; acc.y *= inv; acc.z *= inv; acc.w *= inv;
    }
    *(float4*)(out + (size_t)row * D + c4) = acc;
}

// ---------------------------------------------------------------------------
extern "C" void kernel_launch(void* const* d_in, const int* in_sizes, int n_in,
                              void* d_out, int out_size)
{
    const float* hp         = (const float*)d_in[0];
    const float* hq         = (const float*)d_in[1];
    const float* a_cons     = (const float*)d_in[2];
    const float* a_prod     = (const float*)d_in[3];
    const float* a_rev_cons = (const float*)d_in[4];
    const float* a_rev_prod = (const float*)d_in[5];
    const float* w[12];
    const float* b[12];
    for (int i = 0; i < 12; i++) {
        w[i] = (const float*)d_in[6 + 2 * i];
        b[i] = (const float*)d_in[7 + 2 * i];
    }
    float* out = (float*)d_out;

    // Opt in to >48KB dynamic smem (idempotent; safe under graph capture).
    cudaFuncSetAttribute(gemm6_mma, cudaFuncAttributeMaxDynamicSharedMemorySize,
                         GEMM_SMEM_BYTES);

    void* symp = nullptr;
    cudaGetSymbolAddress(&symp, g_buf);
    float* B0 = (float*)symp;
    #define BUF(i) (B0 + (size_t)(i) * N_NODES * D)
    #define BUFH(i) ((__half*)BUF(i))

    // adjacency ELL: 0=a_cons, 1=a_prod, 2=a_rev_cons, 3=a_rev_prod
    extract_kernel<<<4 * N_NODES / 8, 256>>>(a_cons, a_prod, a_rev_cons, a_rev_prod);

    dim3 gg(12, N_NODES / 128), gb(256);
    // ---- layer 1 (K = 512) ----
    // mats: 0 self(hp,fp32)->BUF0, 1 prod(fp16)->BUF4, 2 rcons(fp16)->BUF5,
    //       3 self(hq,fp32)->BUF1, 4 cons(fp16)->BUF2, 5 rprod(fp16)->BUF3
    gemm6_mma<<<gg, gb, GEMM_SMEM_BYTES>>>(hp, hq,
                          w[0], w[4], w[5], w[1], w[2], w[3],
                          b[0], b[4], b[5], b[1], b[2], b[3],
                          BUF(0), BUF(4), BUF(5), BUF(1), BUF(2), BUF(3), 512);
    // hp1 = act(BUF0 + a_cons@BUF2h + a_rev_prod@BUF3h) ; hq1 analogous
    combine2x_kernel<<<4096, 256>>>(
        BUF(0), BUFH(2), BUFH(3), 0, 3, BUF(6),
        BUF(1), BUFH(4), BUFH(5), 1, 2, BUF(7), 0);

    // ---- layer 2 (K = 256) ----
    gemm6_mma<<<gg, gb, GEMM_SMEM_BYTES>>>(BUF(6), BUF(7),
                          w[6], w[10], w[11], w[7], w[8], w[9],
                          b[6], b[10], b[11], b[7], b[8], b[9],
                          BUF(0), BUF(4), BUF(5), BUF(1), BUF(2), BUF(3), 256);
    combine2x_kernel<<<4096, 256>>>(
        BUF(0), BUFH(2), BUFH(3), 0, 3, out,
        BUF(1), BUFH(4), BUFH(5), 1, 2, out + (size_t)N_NODES * D, 1);
    #undef BUF
    #undef BUFH
}